// round 1
// baseline (speedup 1.0000x reference)
#include <cuda_runtime.h>
#include <math.h>

#define T_TOK 4096
#define CDIM  1024
#define HDIM  4096
#define EDIM  8

// ---- device scratch (allocation-free; __device__ globals are the sanctioned path) ----
__device__ float g_gate_sums[EDIM];
__device__ int   g_cnt[EDIM];
__device__ int   g_bucket_tok[EDIM * T_TOK];
__device__ int   g_pair_slot[T_TOK * 2];
__device__ float g_pair_gate[T_TOK * 2];
__device__ float g_H[(size_t)EDIM * T_TOK * HDIM];  // 512 MB capacity layout [E][4096][H]
__device__ float g_Y[(size_t)EDIM * T_TOK * CDIM];  // 128 MB

// ---------------------------------------------------------------------------
__global__ void init_kernel() {
    int i = threadIdx.x;
    if (i < EDIM) { g_gate_sums[i] = 0.0f; g_cnt[i] = 0; }
}

// One block (128 threads) per token: logits, gumbel-softmax, top-2, bucketing.
__global__ void gate_kernel(const float* __restrict__ x,
                            const float* __restrict__ gumbel,
                            const float* __restrict__ gw,
                            const float* __restrict__ gb) {
    const int t   = blockIdx.x;
    const int tid = threadIdx.x;

    float acc[EDIM];
#pragma unroll
    for (int e = 0; e < EDIM; e++) acc[e] = 0.0f;

    const float* xr = x + (size_t)t * CDIM;
    for (int i = tid; i < CDIM; i += 128) {
        float xv = xr[i];
#pragma unroll
        for (int e = 0; e < EDIM; e++) acc[e] += xv * gw[i * EDIM + e];
    }

    __shared__ float red[128][EDIM];
#pragma unroll
    for (int e = 0; e < EDIM; e++) red[tid][e] = acc[e];
    __syncthreads();
    for (int s = 64; s > 0; s >>= 1) {
        if (tid < s) {
#pragma unroll
            for (int e = 0; e < EDIM; e++) red[tid][e] += red[tid + s][e];
        }
        __syncthreads();
    }

    if (tid == 0) {
        float l[EDIM];
        float mx = -1e30f;
#pragma unroll
        for (int e = 0; e < EDIM; e++) {
            l[e] = red[0][e] + gb[e] + gumbel[t * EDIM + e];  // TAU = 1
            mx = fmaxf(mx, l[e]);
        }
        float sum = 0.0f;
#pragma unroll
        for (int e = 0; e < EDIM; e++) { l[e] = expf(l[e] - mx); sum += l[e]; }
        float inv = 1.0f / sum;
        float g[EDIM];
#pragma unroll
        for (int e = 0; e < EDIM; e++) {
            g[e] = l[e] * inv;
            atomicAdd(&g_gate_sums[e], g[e]);
        }
        // top-2
        int i0 = 0;
#pragma unroll
        for (int e = 1; e < EDIM; e++) if (g[e] > g[i0]) i0 = e;
        int i1 = (i0 == 0) ? 1 : 0;
#pragma unroll
        for (int e = 0; e < EDIM; e++) if (e != i0 && g[e] > g[i1]) i1 = e;

        int p0 = atomicAdd(&g_cnt[i0], 1);
        g_bucket_tok[i0 * T_TOK + p0] = t;
        g_pair_slot[t * 2 + 0] = i0 * T_TOK + p0;
        g_pair_gate[t * 2 + 0] = g[i0];

        int p1 = atomicAdd(&g_cnt[i1], 1);
        g_bucket_tok[i1 * T_TOK + p1] = t;
        g_pair_slot[t * 2 + 1] = i1 * T_TOK + p1;
        g_pair_gate[t * 2 + 1] = g[i1];
    }
}

// ---------------------------------------------------------------------------
// GEMM1: per expert, gathered X[Te,1024] @ w1[e][1024,4096] + b1, exact GELU -> g_H
// 64x64 tile, BK=16, 128 threads, 8x4 microtile.
__global__ __launch_bounds__(128) void gemm1_kernel(const float* __restrict__ x,
                                                    const float* __restrict__ w1,
                                                    const float* __restrict__ b1) {
    const int e  = blockIdx.z;
    const int m0 = blockIdx.y * 64;
    const int n0 = blockIdx.x * 64;
    const int cnt = g_cnt[e];
    if (m0 >= cnt) return;

    __shared__ __align__(16) float As[16][72];
    __shared__ __align__(16) float Bs[16][64];

    const int tid = threadIdx.x;
    const int tx = tid & 15;   // col group (x4)
    const int ty = tid >> 4;   // row group (x8)

    // two A-load quads per thread
    int arow[2], akq[2], tok[2];
#pragma unroll
    for (int l = 0; l < 2; l++) {
        int q = tid * 2 + l;
        arow[l] = q >> 2;
        akq[l]  = q & 3;
        int rg = m0 + arow[l];
        tok[l] = g_bucket_tok[e * T_TOK + ((rg < cnt) ? rg : (cnt - 1))];
    }

    const float* wbase = w1 + (size_t)e * CDIM * HDIM;

    float acc[8][4];
#pragma unroll
    for (int i = 0; i < 8; i++)
#pragma unroll
        for (int j = 0; j < 4; j++) acc[i][j] = 0.0f;

    for (int k0 = 0; k0 < CDIM; k0 += 16) {
#pragma unroll
        for (int l = 0; l < 2; l++) {
            float4 av = *reinterpret_cast<const float4*>(
                x + (size_t)tok[l] * CDIM + k0 + akq[l] * 4);
            As[akq[l] * 4 + 0][arow[l]] = av.x;
            As[akq[l] * 4 + 1][arow[l]] = av.y;
            As[akq[l] * 4 + 2][arow[l]] = av.z;
            As[akq[l] * 4 + 3][arow[l]] = av.w;
        }
#pragma unroll
        for (int l = 0; l < 2; l++) {
            int q = tid * 2 + l;
            int r = q >> 4, c4 = q & 15;
            float4 bv = *reinterpret_cast<const float4*>(
                wbase + (size_t)(k0 + r) * HDIM + n0 + c4 * 4);
            *reinterpret_cast<float4*>(&Bs[r][c4 * 4]) = bv;
        }
        __syncthreads();
#pragma unroll
        for (int k = 0; k < 16; k++) {
            float4 a0 = *reinterpret_cast<const float4*>(&As[k][ty * 8]);
            float4 a1 = *reinterpret_cast<const float4*>(&As[k][ty * 8 + 4]);
            float4 b  = *reinterpret_cast<const float4*>(&Bs[k][tx * 4]);
            float av[8] = {a0.x, a0.y, a0.z, a0.w, a1.x, a1.y, a1.z, a1.w};
            float bv[4] = {b.x, b.y, b.z, b.w};
#pragma unroll
            for (int i = 0; i < 8; i++)
#pragma unroll
                for (int j = 0; j < 4; j++) acc[i][j] += av[i] * bv[j];
        }
        __syncthreads();
    }

    // epilogue: +b1, exact GELU, store
    float4 bb = *reinterpret_cast<const float4*>(b1 + (size_t)e * HDIM + n0 + tx * 4);
#pragma unroll
    for (int i = 0; i < 8; i++) {
        int rg = m0 + ty * 8 + i;
        if (rg >= cnt) continue;
        int slot = e * T_TOK + rg;
        float v0 = acc[i][0] + bb.x;
        float v1 = acc[i][1] + bb.y;
        float v2 = acc[i][2] + bb.z;
        float v3 = acc[i][3] + bb.w;
        float4 o;
        o.x = 0.5f * v0 * (1.0f + erff(v0 * 0.70710678118654752f));
        o.y = 0.5f * v1 * (1.0f + erff(v1 * 0.70710678118654752f));
        o.z = 0.5f * v2 * (1.0f + erff(v2 * 0.70710678118654752f));
        o.w = 0.5f * v3 * (1.0f + erff(v3 * 0.70710678118654752f));
        *reinterpret_cast<float4*>(&g_H[(size_t)slot * HDIM + n0 + tx * 4]) = o;
    }
}

// ---------------------------------------------------------------------------
// GEMM2: per expert, H[Te,4096] @ w2[e][4096,1024] + b2 -> g_Y
__global__ __launch_bounds__(128) void gemm2_kernel(const float* __restrict__ w2,
                                                    const float* __restrict__ b2) {
    const int e  = blockIdx.z;
    const int m0 = blockIdx.y * 64;
    const int n0 = blockIdx.x * 64;
    const int cnt = g_cnt[e];
    if (m0 >= cnt) return;

    __shared__ __align__(16) float As[16][72];
    __shared__ __align__(16) float Bs[16][64];

    const int tid = threadIdx.x;
    const int tx = tid & 15;
    const int ty = tid >> 4;

    int arow[2], akq[2], slotA[2];
#pragma unroll
    for (int l = 0; l < 2; l++) {
        int q = tid * 2 + l;
        arow[l] = q >> 2;
        akq[l]  = q & 3;
        int rg = m0 + arow[l];
        slotA[l] = e * T_TOK + ((rg < cnt) ? rg : (cnt - 1));
    }

    const float* wbase = w2 + (size_t)e * HDIM * CDIM;

    float acc[8][4];
#pragma unroll
    for (int i = 0; i < 8; i++)
#pragma unroll
        for (int j = 0; j < 4; j++) acc[i][j] = 0.0f;

    for (int k0 = 0; k0 < HDIM; k0 += 16) {
#pragma unroll
        for (int l = 0; l < 2; l++) {
            float4 av = *reinterpret_cast<const float4*>(
                &g_H[(size_t)slotA[l] * HDIM + k0 + akq[l] * 4]);
            As[akq[l] * 4 + 0][arow[l]] = av.x;
            As[akq[l] * 4 + 1][arow[l]] = av.y;
            As[akq[l] * 4 + 2][arow[l]] = av.z;
            As[akq[l] * 4 + 3][arow[l]] = av.w;
        }
#pragma unroll
        for (int l = 0; l < 2; l++) {
            int q = tid * 2 + l;
            int r = q >> 4, c4 = q & 15;
            float4 bv = *reinterpret_cast<const float4*>(
                wbase + (size_t)(k0 + r) * CDIM + n0 + c4 * 4);
            *reinterpret_cast<float4*>(&Bs[r][c4 * 4]) = bv;
        }
        __syncthreads();
#pragma unroll
        for (int k = 0; k < 16; k++) {
            float4 a0 = *reinterpret_cast<const float4*>(&As[k][ty * 8]);
            float4 a1 = *reinterpret_cast<const float4*>(&As[k][ty * 8 + 4]);
            float4 b  = *reinterpret_cast<const float4*>(&Bs[k][tx * 4]);
            float av[8] = {a0.x, a0.y, a0.z, a0.w, a1.x, a1.y, a1.z, a1.w};
            float bv[4] = {b.x, b.y, b.z, b.w};
#pragma unroll
            for (int i = 0; i < 8; i++)
#pragma unroll
                for (int j = 0; j < 4; j++) acc[i][j] += av[i] * bv[j];
        }
        __syncthreads();
    }

    float4 bb = *reinterpret_cast<const float4*>(b2 + (size_t)e * CDIM + n0 + tx * 4);
#pragma unroll
    for (int i = 0; i < 8; i++) {
        int rg = m0 + ty * 8 + i;
        if (rg >= cnt) continue;
        int slot = e * T_TOK + rg;
        float4 o;
        o.x = acc[i][0] + bb.x;
        o.y = acc[i][1] + bb.y;
        o.z = acc[i][2] + bb.z;
        o.w = acc[i][3] + bb.w;
        *reinterpret_cast<float4*>(&g_Y[(size_t)slot * CDIM + n0 + tx * 4]) = o;
    }
}

// ---------------------------------------------------------------------------
__global__ void combine_kernel(float* __restrict__ out) {
    const int t = blockIdx.x;
    const int c = threadIdx.x * 4;  // 256 threads cover 1024 cols
    int   s0 = g_pair_slot[t * 2 + 0];
    int   s1 = g_pair_slot[t * 2 + 1];
    float g0 = g_pair_gate[t * 2 + 0];
    float g1 = g_pair_gate[t * 2 + 1];
    float4 y0 = *reinterpret_cast<const float4*>(&g_Y[(size_t)s0 * CDIM + c]);
    float4 y1 = *reinterpret_cast<const float4*>(&g_Y[(size_t)s1 * CDIM + c]);
    float4 o;
    o.x = g0 * y0.x + g1 * y1.x;
    o.y = g0 * y0.y + g1 * y1.y;
    o.z = g0 * y0.z + g1 * y1.z;
    o.w = g0 * y0.w + g1 * y1.w;
    *reinterpret_cast<float4*>(&out[(size_t)t * CDIM + c]) = o;
}

__global__ void loss_kernel(float* __restrict__ out, int out_size) {
    if (threadIdx.x == 0 && out_size > T_TOK * CDIM) {
        float l = 0.0f;
#pragma unroll
        for (int e = 0; e < EDIM; e++) {
            float m = g_gate_sums[e] / (float)T_TOK;
            l += m * logf(m + 1e-8f);
        }
        out[T_TOK * CDIM] = l;
    }
}

// ---------------------------------------------------------------------------
extern "C" void kernel_launch(void* const* d_in, const int* in_sizes, int n_in,
                              void* d_out, int out_size) {
    const float* x      = (const float*)d_in[0];
    const float* gumbel = (const float*)d_in[1];
    const float* gate_w = (const float*)d_in[2];
    const float* gate_b = (const float*)d_in[3];
    const float* w1     = (const float*)d_in[4];
    const float* b1     = (const float*)d_in[5];
    const float* w2     = (const float*)d_in[6];
    const float* b2     = (const float*)d_in[7];
    float* out = (float*)d_out;

    init_kernel<<<1, 32>>>();
    gate_kernel<<<T_TOK, 128>>>(x, gumbel, gate_w, gate_b);
    gemm1_kernel<<<dim3(HDIM / 64, T_TOK / 64, EDIM), 128>>>(x, w1, b1);
    gemm2_kernel<<<dim3(CDIM / 64, T_TOK / 64, EDIM), 128>>>(w2, b2);
    combine_kernel<<<T_TOK, 256>>>(out);
    loss_kernel<<<1, 32>>>(out, out_size);
}